// round 3
// baseline (speedup 1.0000x reference)
#include <cuda_runtime.h>
#include <cstdint>

#define NB 32
#define NH 512
#define NW 512
#define NHW (NH * NW)          // 262144
#define PARTS 64
#define CHUNK (NHW / PARTS)    // 4096
#define FOV 160.0f             // 0.3125 * 512
#define KCONST 106.496f        // 0.208  * 512

// scratch (no allocations allowed)
__device__ float g_part[NB * PARTS * 3];
__device__ float g_params[NB * 8];   // xg, yg, fov_eff, coef, denom, addc

// ---------------------------------------------------------------------------
// Kernel 1: per-(batch, part) partial sums of S, S*r, S*r^2
// grid = (PARTS, NB) = 2048 blocks x 256 -> full-chip occupancy
// ---------------------------------------------------------------------------
__global__ void __launch_bounds__(256) sal_reduce_kernel(
    const float* __restrict__ sal, const float* __restrict__ gaze)
{
    const int b = blockIdx.y;
    const int p = blockIdx.x;
    const float xg = __ldg(&gaze[2 * b]);
    const float yg = __ldg(&gaze[2 * b + 1]);
    const float4* S4 = (const float4*)(sal + (size_t)b * NHW + (size_t)p * CHUNK);
    const int base_lin = p * CHUNK;

    float s0 = 0.f, s1 = 0.f, s2 = 0.f;
    #pragma unroll
    for (int it = 0; it < CHUNK / 4 / 256; it++) {
        int i = it * 256 + threadIdx.x;
        float4 v = __ldg(&S4[i]);
        int lin = base_lin + i * 4;
        float dy = (float)(lin >> 9) - yg;
        float dy2 = fmaf(dy, dy, 1e-6f);
        int x0 = lin & 511;
        #pragma unroll
        for (int k = 0; k < 4; k++) {
            float dx = (float)(x0 + k) - xg;
            float r  = sqrtf(fmaf(dx, dx, dy2));
            float sv = (&v.x)[k];
            s0 += sv;
            s1 = fmaf(sv, r, s1);
            s2 = fmaf(sv * r, r, s2);
        }
    }

    // block reduction
    __shared__ float sh[3][8];
    #pragma unroll
    for (int off = 16; off; off >>= 1) {
        s0 += __shfl_down_sync(0xffffffffu, s0, off);
        s1 += __shfl_down_sync(0xffffffffu, s1, off);
        s2 += __shfl_down_sync(0xffffffffu, s2, off);
    }
    const int wid = threadIdx.x >> 5, lane = threadIdx.x & 31;
    if (lane == 0) { sh[0][wid] = s0; sh[1][wid] = s1; sh[2][wid] = s2; }
    __syncthreads();
    if (wid == 0) {
        s0 = (lane < 8) ? sh[0][lane] : 0.f;
        s1 = (lane < 8) ? sh[1][lane] : 0.f;
        s2 = (lane < 8) ? sh[2][lane] : 0.f;
        #pragma unroll
        for (int off = 4; off; off >>= 1) {
            s0 += __shfl_down_sync(0xffffffffu, s0, off);
            s1 += __shfl_down_sync(0xffffffffu, s1, off);
            s2 += __shfl_down_sync(0xffffffffu, s2, off);
        }
        if (lane == 0) {
            float* dst = &g_part[(b * PARTS + p) * 3];
            dst[0] = s0; dst[1] = s1; dst[2] = s2;
        }
    }
}

// ---------------------------------------------------------------------------
// Kernel 2: finalize per-batch parameters (one thread per batch)
// ---------------------------------------------------------------------------
__global__ void finalize_kernel(const float* __restrict__ gaze)
{
    const int b = threadIdx.x;
    if (b >= NB) return;
    float s0 = 0.f, s1 = 0.f, s2 = 0.f;
    #pragma unroll
    for (int p = 0; p < PARTS; p++) {
        const float* src = &g_part[(b * PARTS + p) * 3];
        s0 += src[0]; s1 += src[1]; s2 += src[2];
    }
    const float xg = gaze[2 * b];
    const float yg = gaze[2 * b + 1];
    const float inv = 1.0f / (s0 + 1e-6f);
    const float mean_r  = s1 * inv;
    const float mean_r2 = s2 * inv;
    float var = mean_r2 - mean_r * mean_r;
    float std_r = sqrtf(fmaxf(var, 0.0f));

    // r_max is attained at an image corner (r monotone in |dx|,|dy|)
    float mdx = fmaxf(xg, 511.0f - xg);
    float mdy = fmaxf(yg, 511.0f - yg);
    float r_max = sqrtf(mdx * mdx + mdy * mdy + 1e-6f);

    float spread = std_r / r_max;
    float fe = FOV * (1.0f + 0.5f * spread);

    // r_tfm monotone increasing in r (peri slope >= 1, continuous at fe),
    // and r_max (>=362) > fe (<240) always -> max r_tfm = peri(r_max)
    float denom = 2.0f * (fe + KCONST);
    float addc  = (fe - KCONST) * 0.5f;
    float t = r_max + KCONST;
    float rtfm_max = t * t / denom + addc;
    float coef = r_max / (rtfm_max + 1e-6f);

    float* prm = &g_params[b * 8];
    prm[0] = xg; prm[1] = yg; prm[2] = fe; prm[3] = coef;
    prm[4] = denom; prm[5] = addc;
}

// ---------------------------------------------------------------------------
// Kernel 3: warp + bilinear sample + quantize. 4 pixels / thread, float4 store
// ---------------------------------------------------------------------------
__global__ void __launch_bounds__(256) warp_sample_kernel(
    const float* __restrict__ img, float* __restrict__ out)
{
    const int tid  = blockIdx.x * 256 + threadIdx.x;   // one per 4 pixels
    const int pix0 = tid * 4;
    const int b    = pix0 >> 18;
    const int rem  = pix0 & (NHW - 1);
    const int y    = rem >> 9;
    const int x    = rem & 511;   // 512 % 4 == 0 -> all 4 pixels same row

    const float* prm = &g_params[b * 8];
    const float xg    = __ldg(&prm[0]);
    const float yg    = __ldg(&prm[1]);
    const float fe    = __ldg(&prm[2]);
    const float coef  = __ldg(&prm[3]);
    const float denom = __ldg(&prm[4]);
    const float addc  = __ldg(&prm[5]);

    const float dy  = (float)y - yg;
    const float dy2 = dy * dy + 1e-6f;

    float4 res[3];

    #pragma unroll
    for (int p = 0; p < 4; p++) {
        float dx = (float)(x + p) - xg;
        float r  = sqrtf(fmaf(dx, dx, dy2));

        float rt;
        if (r < fe) {
            rt = r;
        } else {
            float t = r + KCONST;
            rt = t * t / denom + addc;
        }
        float rn   = coef * rt;
        float invr = 1.0f / r;
        float Xn = fmaf(dx * invr, rn, xg);
        float Yn = fmaf(dy * invr, rn, yg);

        // reference normalizes to [-1,1] then back — replicate the round trip
        float gx = Xn / 511.0f * 2.0f - 1.0f;
        float gy = Yn / 511.0f * 2.0f - 1.0f;
        float fx = (gx + 1.0f) * 0.5f * 511.0f;
        float fy = (gy + 1.0f) * 0.5f * 511.0f;

        float x0f = floorf(fx), y0f = floorf(fy);
        float x1f = x0f + 1.0f, y1f = y0f + 1.0f;
        float wx1 = fx - x0f, wx0 = 1.0f - wx1;
        float wy1 = fy - y0f, wy0 = 1.0f - wy1;

        bool vx0 = (x0f >= 0.0f) && (x0f <= 511.0f);
        bool vx1 = (x1f >= 0.0f) && (x1f <= 511.0f);
        bool vy0 = (y0f >= 0.0f) && (y0f <= 511.0f);
        bool vy1 = (y1f >= 0.0f) && (y1f <= 511.0f);

        int x0i = (int)fminf(fmaxf(x0f, 0.0f), 511.0f);
        int x1i = (int)fminf(fmaxf(x1f, 0.0f), 511.0f);
        int y0i = (int)fminf(fmaxf(y0f, 0.0f), 511.0f);
        int y1i = (int)fminf(fmaxf(y1f, 0.0f), 511.0f);

        float m00 = (vy0 && vx0) ? (wy0 * wx0) : 0.0f;
        float m01 = (vy0 && vx1) ? (wy0 * wx1) : 0.0f;
        float m10 = (vy1 && vx0) ? (wy1 * wx0) : 0.0f;
        float m11 = (vy1 && vx1) ? (wy1 * wx1) : 0.0f;

        const int o00 = y0i * NW + x0i;
        const int o01 = y0i * NW + x1i;
        const int o10 = y1i * NW + x0i;
        const int o11 = y1i * NW + x1i;

        const float* imb = img + (size_t)b * 3 * NHW;
        #pragma unroll
        for (int c = 0; c < 3; c++) {
            const float* ic = imb + (size_t)c * NHW;
            float v = __ldg(ic + o00) * m00 + __ldg(ic + o01) * m01 +
                      __ldg(ic + o10) * m10 + __ldg(ic + o11) * m11;
            v = fminf(fmaxf(v, 0.0f), 255.0f);
            (&res[c].x)[p] = (float)(int)v;   // u8 quantize (trunc), stored f32
        }
    }

    float* outb = out + (size_t)b * 3 * NHW + rem;
    #pragma unroll
    for (int c = 0; c < 3; c++)
        *(float4*)(outb + (size_t)c * NHW) = res[c];
}

// ---------------------------------------------------------------------------
extern "C" void kernel_launch(void* const* d_in, const int* in_sizes, int n_in,
                              void* d_out, int out_size)
{
    const float* img  = (const float*)d_in[0];
    const float* gaze = (const float*)d_in[1];
    const float* sal  = (const float*)d_in[2];
    float* out = (float*)d_out;

    dim3 g1(PARTS, NB);
    sal_reduce_kernel<<<g1, 256>>>(sal, gaze);
    finalize_kernel<<<1, 32>>>(gaze);
    warp_sample_kernel<<<(NB * NHW) / (256 * 4), 256>>>(img, out);
}

// round 4
// speedup vs baseline: 1.1661x; 1.1661x over previous
#include <cuda_runtime.h>
#include <cstdint>

#define NB 32
#define NH 512
#define NW 512
#define NHW (NH * NW)          // 262144
#define PARTS 64
#define CHUNK (NHW / PARTS)    // 4096
#define FOV 160.0f             // 0.3125 * 512
#define KCONST 106.496f        // 0.208  * 512

// scratch (no allocations allowed)
__device__ float g_part[NB * PARTS * 3];
__device__ float g_params[NB * 8];   // xg, yg, fov_eff, coef, invdenom, addc

// ---------------------------------------------------------------------------
// Kernel 1: per-(batch, part) partial sums of S, S*r, S*r^2
// grid = (PARTS, NB) = 2048 blocks x 256. Loads front-batched (MLP=4).
// ---------------------------------------------------------------------------
__global__ void __launch_bounds__(256) sal_reduce_kernel(
    const float* __restrict__ sal, const float* __restrict__ gaze)
{
    const int b = blockIdx.y;
    const int p = blockIdx.x;
    const float xg = __ldg(&gaze[2 * b]);
    const float yg = __ldg(&gaze[2 * b + 1]);
    const float4* S4 = (const float4*)(sal + (size_t)b * NHW + (size_t)p * CHUNK);
    const int base_lin = p * CHUNK;

    // front-batch all 4 LDG.128s for memory-level parallelism
    float4 v[4];
    #pragma unroll
    for (int it = 0; it < 4; it++)
        v[it] = __ldg(&S4[it * 256 + threadIdx.x]);

    float s0 = 0.f, s1 = 0.f, s2 = 0.f;
    #pragma unroll
    for (int it = 0; it < 4; it++) {
        int lin = base_lin + (it * 256 + threadIdx.x) * 4;
        float dy = (float)(lin >> 9) - yg;
        float dy2 = fmaf(dy, dy, 1e-6f);
        int x0 = lin & 511;
        #pragma unroll
        for (int k = 0; k < 4; k++) {
            float dx = (float)(x0 + k) - xg;
            float d2 = fmaf(dx, dx, dy2);
            float r  = d2 * rsqrtf(d2);       // r = sqrt(d2), 1 MUFU
            float sv = (&v[it].x)[k];
            s0 += sv;
            s1 = fmaf(sv, r, s1);
            s2 = fmaf(sv * r, r, s2);
        }
    }

    // block reduction
    __shared__ float sh[3][8];
    #pragma unroll
    for (int off = 16; off; off >>= 1) {
        s0 += __shfl_down_sync(0xffffffffu, s0, off);
        s1 += __shfl_down_sync(0xffffffffu, s1, off);
        s2 += __shfl_down_sync(0xffffffffu, s2, off);
    }
    const int wid = threadIdx.x >> 5, lane = threadIdx.x & 31;
    if (lane == 0) { sh[0][wid] = s0; sh[1][wid] = s1; sh[2][wid] = s2; }
    __syncthreads();
    if (wid == 0) {
        s0 = (lane < 8) ? sh[0][lane] : 0.f;
        s1 = (lane < 8) ? sh[1][lane] : 0.f;
        s2 = (lane < 8) ? sh[2][lane] : 0.f;
        #pragma unroll
        for (int off = 4; off; off >>= 1) {
            s0 += __shfl_down_sync(0xffffffffu, s0, off);
            s1 += __shfl_down_sync(0xffffffffu, s1, off);
            s2 += __shfl_down_sync(0xffffffffu, s2, off);
        }
        if (lane == 0) {
            float* dst = &g_part[(b * PARTS + p) * 3];
            dst[0] = s0; dst[1] = s1; dst[2] = s2;
        }
    }
}

// ---------------------------------------------------------------------------
// Kernel 2: finalize per-batch parameters (one thread per batch)
// ---------------------------------------------------------------------------
__global__ void finalize_kernel(const float* __restrict__ gaze)
{
    const int b = threadIdx.x;
    if (b >= NB) return;
    float s0 = 0.f, s1 = 0.f, s2 = 0.f;
    #pragma unroll
    for (int p = 0; p < PARTS; p++) {
        const float* src = &g_part[(b * PARTS + p) * 3];
        s0 += src[0]; s1 += src[1]; s2 += src[2];
    }
    const float xg = gaze[2 * b];
    const float yg = gaze[2 * b + 1];
    const float inv = 1.0f / (s0 + 1e-6f);
    const float mean_r  = s1 * inv;
    const float mean_r2 = s2 * inv;
    float var = mean_r2 - mean_r * mean_r;
    float std_r = sqrtf(fmaxf(var, 0.0f));

    // r_max is attained at an image corner (r monotone in |dx|,|dy|)
    float mdx = fmaxf(xg, 511.0f - xg);
    float mdy = fmaxf(yg, 511.0f - yg);
    float r_max = sqrtf(mdx * mdx + mdy * mdy + 1e-6f);

    float spread = std_r / r_max;
    float fe = FOV * (1.0f + 0.5f * spread);

    // r_tfm monotone increasing in r (peri slope >= 1, continuous at fe),
    // and r_max (>=362) > fe (<240) always -> max r_tfm = peri(r_max)
    float denom = 2.0f * (fe + KCONST);
    float addc  = (fe - KCONST) * 0.5f;
    float t = r_max + KCONST;
    float rtfm_max = t * t / denom + addc;
    float coef = r_max / (rtfm_max + 1e-6f);

    float* prm = &g_params[b * 8];
    prm[0] = xg; prm[1] = yg; prm[2] = fe; prm[3] = coef;
    prm[4] = 1.0f / denom; prm[5] = addc;
}

// ---------------------------------------------------------------------------
// Kernel 3: warp + bilinear sample + quantize. 1 px/thread (lane-stride-1).
// ---------------------------------------------------------------------------
__global__ void __launch_bounds__(256) warp_sample_kernel(
    const float* __restrict__ img, float* __restrict__ out)
{
    const int idx = blockIdx.x * 256 + threadIdx.x;
    const int b   = idx >> 18;
    const int rem = idx & (NHW - 1);
    const int y   = rem >> 9;
    const int x   = rem & 511;

    const float* prm = &g_params[b * 8];
    const float xg     = __ldg(&prm[0]);
    const float yg     = __ldg(&prm[1]);
    const float fe     = __ldg(&prm[2]);
    const float coef   = __ldg(&prm[3]);
    const float invden = __ldg(&prm[4]);
    const float addc   = __ldg(&prm[5]);

    float dx = (float)x - xg;
    float dy = (float)y - yg;
    float d2 = fmaf(dx, dx, fmaf(dy, dy, 1e-6f));
    float invr = rsqrtf(d2);          // 1 MUFU total
    float r    = d2 * invr;

    float t  = r + KCONST;
    float rp = fmaf(t * t, invden, addc);
    float rt = (r < fe) ? r : rp;
    float rn = coef * rt;
    float Xn = fmaf(dx * invr, rn, xg);
    float Yn = fmaf(dy * invr, rn, yg);

    // reference normalizes to [-1,1] then back — replicate the round trip
    float gx = Xn * (1.0f / 511.0f) * 2.0f - 1.0f;
    float gy = Yn * (1.0f / 511.0f) * 2.0f - 1.0f;
    float fx = (gx + 1.0f) * 0.5f * 511.0f;
    float fy = (gy + 1.0f) * 0.5f * 511.0f;

    float x0f = floorf(fx), y0f = floorf(fy);
    float x1f = x0f + 1.0f, y1f = y0f + 1.0f;
    float wx1 = fx - x0f, wx0 = 1.0f - wx1;
    float wy1 = fy - y0f, wy0 = 1.0f - wy1;

    bool vx0 = (x0f >= 0.0f) && (x0f <= 511.0f);
    bool vx1 = (x1f >= 0.0f) && (x1f <= 511.0f);
    bool vy0 = (y0f >= 0.0f) && (y0f <= 511.0f);
    bool vy1 = (y1f >= 0.0f) && (y1f <= 511.0f);

    int x0i = (int)fminf(fmaxf(x0f, 0.0f), 511.0f);
    int x1i = (int)fminf(fmaxf(x1f, 0.0f), 511.0f);
    int y0i = (int)fminf(fmaxf(y0f, 0.0f), 511.0f);
    int y1i = (int)fminf(fmaxf(y1f, 0.0f), 511.0f);

    float m00 = (vy0 && vx0) ? (wy0 * wx0) : 0.0f;
    float m01 = (vy0 && vx1) ? (wy0 * wx1) : 0.0f;
    float m10 = (vy1 && vx0) ? (wy1 * wx0) : 0.0f;
    float m11 = (vy1 && vx1) ? (wy1 * wx1) : 0.0f;

    const int o00 = y0i * NW + x0i;
    const int o01 = y0i * NW + x1i;
    const int o10 = y1i * NW + x0i;
    const int o11 = y1i * NW + x1i;

    const float* imb = img + (size_t)b * 3 * NHW;
    float* outb = out + (size_t)b * 3 * NHW + rem;
    #pragma unroll
    for (int c = 0; c < 3; c++) {
        const float* ic = imb + (size_t)c * NHW;
        float v = __ldg(ic + o00) * m00 + __ldg(ic + o01) * m01 +
                  __ldg(ic + o10) * m10 + __ldg(ic + o11) * m11;
        v = fminf(fmaxf(v, 0.0f), 255.0f);
        // u8 quantization (truncation, matches XLA convert), stored as f32
        outb[(size_t)c * NHW] = (float)(int)v;
    }
}

// ---------------------------------------------------------------------------
extern "C" void kernel_launch(void* const* d_in, const int* in_sizes, int n_in,
                              void* d_out, int out_size)
{
    const float* img  = (const float*)d_in[0];
    const float* gaze = (const float*)d_in[1];
    const float* sal  = (const float*)d_in[2];
    float* out = (float*)d_out;

    dim3 g1(PARTS, NB);
    sal_reduce_kernel<<<g1, 256>>>(sal, gaze);
    finalize_kernel<<<1, 32>>>(gaze);
    warp_sample_kernel<<<(NB * NHW) / 256, 256>>>(img, out);
}

// round 5
// speedup vs baseline: 1.1758x; 1.0083x over previous
#include <cuda_runtime.h>
#include <cstdint>

#define NB 32
#define NH 512
#define NW 512
#define NHW (NH * NW)          // 262144
#define PARTS 32
#define CHUNK (NHW / PARTS)    // 8192
#define FOV 160.0f             // 0.3125 * 512
#define KCONST 106.496f        // 0.208  * 512

// scratch (no allocations allowed)
__device__ float g_part[NB * PARTS * 3];
__device__ float g_params[NB * 8];   // xg, yg, fov_eff, coef, invdenom, addc

// ---------------------------------------------------------------------------
// Kernel 1: per-(batch, part) partial sums of S, S*r, S*r^2
// grid = (PARTS, NB) = 1024 blocks x 256. 8 front-batched LDG.128 (MLP=8).
// ---------------------------------------------------------------------------
__global__ void __launch_bounds__(256) sal_reduce_kernel(
    const float* __restrict__ sal, const float* __restrict__ gaze)
{
    const int b = blockIdx.y;
    const int p = blockIdx.x;
    const float xg = __ldg(&gaze[2 * b]);
    const float yg = __ldg(&gaze[2 * b + 1]);
    const float4* S4 = (const float4*)(sal + (size_t)b * NHW + (size_t)p * CHUNK);
    const int base_lin = p * CHUNK;

    // front-batch all 8 LDG.128s for memory-level parallelism
    float4 v[8];
    #pragma unroll
    for (int it = 0; it < 8; it++)
        v[it] = __ldg(&S4[it * 256 + threadIdx.x]);

    float s0 = 0.f, s1 = 0.f, s2 = 0.f;
    #pragma unroll
    for (int it = 0; it < 8; it++) {
        int lin = base_lin + (it * 256 + threadIdx.x) * 4;
        float dy = (float)(lin >> 9) - yg;
        float dy2 = fmaf(dy, dy, 1e-6f);
        int x0 = lin & 511;
        #pragma unroll
        for (int k = 0; k < 4; k++) {
            float dx = (float)(x0 + k) - xg;
            float d2 = fmaf(dx, dx, dy2);
            float r  = d2 * rsqrtf(d2);       // r = sqrt(d2), 1 MUFU
            float sv = (&v[it].x)[k];
            s0 += sv;
            s1 = fmaf(sv, r, s1);
            s2 = fmaf(sv * r, r, s2);
        }
    }

    // block reduction
    __shared__ float sh[3][8];
    #pragma unroll
    for (int off = 16; off; off >>= 1) {
        s0 += __shfl_down_sync(0xffffffffu, s0, off);
        s1 += __shfl_down_sync(0xffffffffu, s1, off);
        s2 += __shfl_down_sync(0xffffffffu, s2, off);
    }
    const int wid = threadIdx.x >> 5, lane = threadIdx.x & 31;
    if (lane == 0) { sh[0][wid] = s0; sh[1][wid] = s1; sh[2][wid] = s2; }
    __syncthreads();
    if (wid == 0) {
        s0 = (lane < 8) ? sh[0][lane] : 0.f;
        s1 = (lane < 8) ? sh[1][lane] : 0.f;
        s2 = (lane < 8) ? sh[2][lane] : 0.f;
        #pragma unroll
        for (int off = 4; off; off >>= 1) {
            s0 += __shfl_down_sync(0xffffffffu, s0, off);
            s1 += __shfl_down_sync(0xffffffffu, s1, off);
            s2 += __shfl_down_sync(0xffffffffu, s2, off);
        }
        if (lane == 0) {
            float* dst = &g_part[(b * PARTS + p) * 3];
            dst[0] = s0; dst[1] = s1; dst[2] = s2;
        }
    }
}

// ---------------------------------------------------------------------------
// Kernel 2: finalize per-batch parameters (one thread per batch)
// ---------------------------------------------------------------------------
__global__ void finalize_kernel(const float* __restrict__ gaze)
{
    const int b = threadIdx.x;
    if (b >= NB) return;
    float s0 = 0.f, s1 = 0.f, s2 = 0.f;
    #pragma unroll
    for (int p = 0; p < PARTS; p++) {
        const float* src = &g_part[(b * PARTS + p) * 3];
        s0 += src[0]; s1 += src[1]; s2 += src[2];
    }
    const float xg = gaze[2 * b];
    const float yg = gaze[2 * b + 1];
    const float inv = 1.0f / (s0 + 1e-6f);
    const float mean_r  = s1 * inv;
    const float mean_r2 = s2 * inv;
    float var = mean_r2 - mean_r * mean_r;
    float std_r = sqrtf(fmaxf(var, 0.0f));

    // r_max is attained at an image corner (r monotone in |dx|,|dy|)
    float mdx = fmaxf(xg, 511.0f - xg);
    float mdy = fmaxf(yg, 511.0f - yg);
    float r_max = sqrtf(mdx * mdx + mdy * mdy + 1e-6f);

    float spread = std_r / r_max;
    float fe = FOV * (1.0f + 0.5f * spread);

    // r_tfm monotone increasing in r (peri slope >= 1, continuous at fe),
    // and r_max (>=362) > fe (<240) always -> max r_tfm = peri(r_max)
    float denom = 2.0f * (fe + KCONST);
    float addc  = (fe - KCONST) * 0.5f;
    float t = r_max + KCONST;
    float rtfm_max = t * t / denom + addc;
    float coef = r_max / (rtfm_max + 1e-6f);

    float* prm = &g_params[b * 8];
    prm[0] = xg; prm[1] = yg; prm[2] = fe; prm[3] = coef;
    prm[4] = 1.0f / denom; prm[5] = addc;
}

// ---------------------------------------------------------------------------
// Kernel 3: warp + bilinear sample + quantize. 1 px/thread, gathers batched.
// ---------------------------------------------------------------------------
__global__ void __launch_bounds__(256) warp_sample_kernel(
    const float* __restrict__ img, float* __restrict__ out)
{
    const int idx = blockIdx.x * 256 + threadIdx.x;
    const int b   = idx >> 18;
    const int rem = idx & (NHW - 1);
    const int y   = rem >> 9;
    const int x   = rem & 511;

    const float* prm = &g_params[b * 8];
    const float xg     = __ldg(&prm[0]);
    const float yg     = __ldg(&prm[1]);
    const float fe     = __ldg(&prm[2]);
    const float coef   = __ldg(&prm[3]);
    const float invden = __ldg(&prm[4]);
    const float addc   = __ldg(&prm[5]);

    float dx = (float)x - xg;
    float dy = (float)y - yg;
    float d2 = fmaf(dx, dx, fmaf(dy, dy, 1e-6f));
    float invr = rsqrtf(d2);          // 1 MUFU total
    float r    = d2 * invr;

    float t  = r + KCONST;
    float rp = fmaf(t * t, invden, addc);
    float rt = (r < fe) ? r : rp;
    float rn = coef * rt;
    float Xn = fmaf(dx * invr, rn, xg);
    float Yn = fmaf(dy * invr, rn, yg);

    // reference normalizes to [-1,1] then back — replicate the round trip
    float gx = Xn * (1.0f / 511.0f) * 2.0f - 1.0f;
    float gy = Yn * (1.0f / 511.0f) * 2.0f - 1.0f;
    float fx = (gx + 1.0f) * 0.5f * 511.0f;
    float fy = (gy + 1.0f) * 0.5f * 511.0f;

    float x0f = floorf(fx), y0f = floorf(fy);
    float x1f = x0f + 1.0f, y1f = y0f + 1.0f;
    float wx1 = fx - x0f, wx0 = 1.0f - wx1;
    float wy1 = fy - y0f, wy0 = 1.0f - wy1;

    bool vx0 = (x0f >= 0.0f) && (x0f <= 511.0f);
    bool vx1 = (x1f >= 0.0f) && (x1f <= 511.0f);
    bool vy0 = (y0f >= 0.0f) && (y0f <= 511.0f);
    bool vy1 = (y1f >= 0.0f) && (y1f <= 511.0f);

    int x0i = (int)fminf(fmaxf(x0f, 0.0f), 511.0f);
    int x1i = (int)fminf(fmaxf(x1f, 0.0f), 511.0f);
    int y0i = (int)fminf(fmaxf(y0f, 0.0f), 511.0f);
    int y1i = (int)fminf(fmaxf(y1f, 0.0f), 511.0f);

    float m00 = (vy0 && vx0) ? (wy0 * wx0) : 0.0f;
    float m01 = (vy0 && vx1) ? (wy0 * wx1) : 0.0f;
    float m10 = (vy1 && vx0) ? (wy1 * wx0) : 0.0f;
    float m11 = (vy1 && vx1) ? (wy1 * wx1) : 0.0f;

    const int o00 = y0i * NW + x0i;
    const int o01 = y0i * NW + x1i;
    const int o10 = y1i * NW + x0i;
    const int o11 = y1i * NW + x1i;

    // front-batch all 12 gather loads (MLP = 12) before any blending math
    const float* imb = img + (size_t)b * 3 * NHW;
    float g[12];
    #pragma unroll
    for (int c = 0; c < 3; c++) {
        const float* ic = imb + (size_t)c * NHW;
        g[c * 4 + 0] = __ldg(ic + o00);
        g[c * 4 + 1] = __ldg(ic + o01);
        g[c * 4 + 2] = __ldg(ic + o10);
        g[c * 4 + 3] = __ldg(ic + o11);
    }

    float* outb = out + (size_t)b * 3 * NHW + rem;
    #pragma unroll
    for (int c = 0; c < 3; c++) {
        float v = g[c * 4 + 0] * m00 + g[c * 4 + 1] * m01 +
                  g[c * 4 + 2] * m10 + g[c * 4 + 3] * m11;
        v = fminf(fmaxf(v, 0.0f), 255.0f);
        // u8 quantization (truncation, matches XLA convert), stored as f32
        outb[(size_t)c * NHW] = (float)(int)v;
    }
}

// ---------------------------------------------------------------------------
extern "C" void kernel_launch(void* const* d_in, const int* in_sizes, int n_in,
                              void* d_out, int out_size)
{
    const float* img  = (const float*)d_in[0];
    const float* gaze = (const float*)d_in[1];
    const float* sal  = (const float*)d_in[2];
    float* out = (float*)d_out;

    dim3 g1(PARTS, NB);
    sal_reduce_kernel<<<g1, 256>>>(sal, gaze);
    finalize_kernel<<<1, 32>>>(gaze);
    warp_sample_kernel<<<(NB * NHW) / 256, 256>>>(img, out);
}

// round 6
// speedup vs baseline: 1.2568x; 1.0689x over previous
#include <cuda_runtime.h>
#include <cstdint>

#define NB 32
#define NH 512
#define NW 512
#define NHW (NH * NW)          // 262144
#define PARTS 64
#define CHUNK (NHW / PARTS)    // 4096
#define FOV 160.0f             // 0.3125 * 512
#define KCONST 106.496f        // 0.208  * 512

// scratch (no allocations allowed)
__device__ float g_part[NB * PARTS * 3];

// ---------------------------------------------------------------------------
// Kernel 1: per-(batch, part) partial sums of S, S*r, S*r^2
// grid = (PARTS, NB) = 2048 blocks x 256. 4 front-batched LDG.128 (MLP=4).
// ---------------------------------------------------------------------------
__global__ void __launch_bounds__(256) sal_reduce_kernel(
    const float* __restrict__ sal, const float* __restrict__ gaze)
{
    const int b = blockIdx.y;
    const int p = blockIdx.x;
    const float xg = __ldg(&gaze[2 * b]);
    const float yg = __ldg(&gaze[2 * b + 1]);
    const float4* S4 = (const float4*)(sal + (size_t)b * NHW + (size_t)p * CHUNK);
    const int base_lin = p * CHUNK;

    // front-batch all 4 LDG.128s for memory-level parallelism
    float4 v[4];
    #pragma unroll
    for (int it = 0; it < 4; it++)
        v[it] = __ldg(&S4[it * 256 + threadIdx.x]);

    float s0 = 0.f, s1 = 0.f, s2 = 0.f;
    #pragma unroll
    for (int it = 0; it < 4; it++) {
        int lin = base_lin + (it * 256 + threadIdx.x) * 4;
        float dy = (float)(lin >> 9) - yg;
        float dy2 = fmaf(dy, dy, 1e-6f);
        int x0 = lin & 511;
        #pragma unroll
        for (int k = 0; k < 4; k++) {
            float dx = (float)(x0 + k) - xg;
            float d2 = fmaf(dx, dx, dy2);
            float r  = d2 * rsqrtf(d2);       // r = sqrt(d2), 1 MUFU
            float sv = (&v[it].x)[k];
            s0 += sv;
            s1 = fmaf(sv, r, s1);
            s2 = fmaf(sv * r, r, s2);
        }
    }

    // block reduction
    __shared__ float sh[3][8];
    #pragma unroll
    for (int off = 16; off; off >>= 1) {
        s0 += __shfl_down_sync(0xffffffffu, s0, off);
        s1 += __shfl_down_sync(0xffffffffu, s1, off);
        s2 += __shfl_down_sync(0xffffffffu, s2, off);
    }
    const int wid = threadIdx.x >> 5, lane = threadIdx.x & 31;
    if (lane == 0) { sh[0][wid] = s0; sh[1][wid] = s1; sh[2][wid] = s2; }
    __syncthreads();
    if (wid == 0) {
        s0 = (lane < 8) ? sh[0][lane] : 0.f;
        s1 = (lane < 8) ? sh[1][lane] : 0.f;
        s2 = (lane < 8) ? sh[2][lane] : 0.f;
        #pragma unroll
        for (int off = 4; off; off >>= 1) {
            s0 += __shfl_down_sync(0xffffffffu, s0, off);
            s1 += __shfl_down_sync(0xffffffffu, s1, off);
            s2 += __shfl_down_sync(0xffffffffu, s2, off);
        }
        if (lane == 0) {
            float* dst = &g_part[(b * PARTS + p) * 3];
            dst[0] = s0; dst[1] = s1; dst[2] = s2;
        }
    }
}

// ---------------------------------------------------------------------------
// Kernel 2: warp + bilinear + quantize.  One block = one (batch,row).
// Each of 256 threads handles pixels x and x+256 in that row.
// Params are recomputed per block from the 64 partial sums (cheap, ~12MB L2
// total) — removes the separate finalize kernel + its launch gap.
// ---------------------------------------------------------------------------
__global__ void __launch_bounds__(256) warp_sample_kernel(
    const float* __restrict__ img, const float* __restrict__ gaze,
    float* __restrict__ out)
{
    const int b = blockIdx.x >> 9;
    const int y = blockIdx.x & 511;

    __shared__ float red[3][2];
    __shared__ float sprm[6];   // xg, yg, fe, coef, invden, addc

    // per-block parameter computation (threads 0..63)
    if (threadIdx.x < 64) {
        const float* src = &g_part[(b * PARTS + threadIdx.x) * 3];
        float a0 = src[0], a1 = src[1], a2 = src[2];
        #pragma unroll
        for (int off = 16; off; off >>= 1) {
            a0 += __shfl_down_sync(0xffffffffu, a0, off);
            a1 += __shfl_down_sync(0xffffffffu, a1, off);
            a2 += __shfl_down_sync(0xffffffffu, a2, off);
        }
        if ((threadIdx.x & 31) == 0) {
            red[0][threadIdx.x >> 5] = a0;
            red[1][threadIdx.x >> 5] = a1;
            red[2][threadIdx.x >> 5] = a2;
        }
    }
    __syncthreads();
    if (threadIdx.x == 0) {
        float s0 = red[0][0] + red[0][1];
        float s1 = red[1][0] + red[1][1];
        float s2 = red[2][0] + red[2][1];
        const float xg = __ldg(&gaze[2 * b]);
        const float yg = __ldg(&gaze[2 * b + 1]);
        float inv = 1.0f / (s0 + 1e-6f);
        float mean_r  = s1 * inv;
        float mean_r2 = s2 * inv;
        float var = mean_r2 - mean_r * mean_r;
        float std_r = sqrtf(fmaxf(var, 0.0f));
        // r_max attained at an image corner (r monotone in |dx|,|dy|)
        float mdx = fmaxf(xg, 511.0f - xg);
        float mdy = fmaxf(yg, 511.0f - yg);
        float r_max = sqrtf(mdx * mdx + mdy * mdy + 1e-6f);
        float fe = FOV * (1.0f + 0.5f * (std_r / r_max));
        // max r_tfm = peri(r_max)  (monotone, r_max > fe always)
        float denom = 2.0f * (fe + KCONST);
        float addc  = (fe - KCONST) * 0.5f;
        float t = r_max + KCONST;
        float rtfm_max = t * t / denom + addc;
        float coef = r_max / (rtfm_max + 1e-6f);
        sprm[0] = xg; sprm[1] = yg; sprm[2] = fe;
        sprm[3] = coef; sprm[4] = 1.0f / denom; sprm[5] = addc;
    }
    __syncthreads();

    const float xg     = sprm[0];
    const float yg     = sprm[1];
    const float fe     = sprm[2];
    const float coef   = sprm[3];
    const float invden = sprm[4];
    const float addc   = sprm[5];

    const float dy  = (float)y - yg;
    const float dy2 = fmaf(dy, dy, 1e-6f);
    const float* imb = img + (size_t)b * 3 * NHW;
    float* outb = out + (size_t)b * 3 * NHW + y * NW;

    int   oo[2][4];
    float mm[2][4];

    #pragma unroll
    for (int p = 0; p < 2; p++) {
        const int x = threadIdx.x + p * 256;
        float dx = (float)x - xg;
        float d2 = fmaf(dx, dx, dy2);
        float invr = rsqrtf(d2);
        float r    = d2 * invr;

        float t  = r + KCONST;
        float rp = fmaf(t * t, invden, addc);
        float rt = (r < fe) ? r : rp;
        float rn = coef * rt;
        float Xn = fmaf(dx * invr, rn, xg);
        float Yn = fmaf(dy * invr, rn, yg);

        // reference normalizes to [-1,1] then back — replicate the round trip
        float gx = Xn * (1.0f / 511.0f) * 2.0f - 1.0f;
        float gy = Yn * (1.0f / 511.0f) * 2.0f - 1.0f;
        float fx = (gx + 1.0f) * 0.5f * 511.0f;
        float fy = (gy + 1.0f) * 0.5f * 511.0f;

        float x0f = floorf(fx), y0f = floorf(fy);
        float x1f = x0f + 1.0f, y1f = y0f + 1.0f;
        float wx1 = fx - x0f, wx0 = 1.0f - wx1;
        float wy1 = fy - y0f, wy0 = 1.0f - wy1;

        bool vx0 = (x0f >= 0.0f) && (x0f <= 511.0f);
        bool vx1 = (x1f >= 0.0f) && (x1f <= 511.0f);
        bool vy0 = (y0f >= 0.0f) && (y0f <= 511.0f);
        bool vy1 = (y1f >= 0.0f) && (y1f <= 511.0f);

        int x0i = (int)fminf(fmaxf(x0f, 0.0f), 511.0f);
        int x1i = (int)fminf(fmaxf(x1f, 0.0f), 511.0f);
        int y0i = (int)fminf(fmaxf(y0f, 0.0f), 511.0f);
        int y1i = (int)fminf(fmaxf(y1f, 0.0f), 511.0f);

        mm[p][0] = (vy0 && vx0) ? (wy0 * wx0) : 0.0f;
        mm[p][1] = (vy0 && vx1) ? (wy0 * wx1) : 0.0f;
        mm[p][2] = (vy1 && vx0) ? (wy1 * wx0) : 0.0f;
        mm[p][3] = (vy1 && vx1) ? (wy1 * wx1) : 0.0f;

        oo[p][0] = y0i * NW + x0i;
        oo[p][1] = y0i * NW + x1i;
        oo[p][2] = y1i * NW + x0i;
        oo[p][3] = y1i * NW + x1i;
    }

    // front-batch all 24 gather loads
    float g[2][12];
    #pragma unroll
    for (int p = 0; p < 2; p++) {
        #pragma unroll
        for (int c = 0; c < 3; c++) {
            const float* ic = imb + (size_t)c * NHW;
            g[p][c * 4 + 0] = __ldg(ic + oo[p][0]);
            g[p][c * 4 + 1] = __ldg(ic + oo[p][1]);
            g[p][c * 4 + 2] = __ldg(ic + oo[p][2]);
            g[p][c * 4 + 3] = __ldg(ic + oo[p][3]);
        }
    }

    #pragma unroll
    for (int p = 0; p < 2; p++) {
        #pragma unroll
        for (int c = 0; c < 3; c++) {
            float v = g[p][c * 4 + 0] * mm[p][0] + g[p][c * 4 + 1] * mm[p][1] +
                      g[p][c * 4 + 2] * mm[p][2] + g[p][c * 4 + 3] * mm[p][3];
            v = fminf(fmaxf(v, 0.0f), 255.0f);
            // u8 quantization (trunc, matches XLA), stored f32, streaming
            __stcs(outb + (size_t)c * NHW + threadIdx.x + p * 256,
                   (float)(int)v);
        }
    }
}

// ---------------------------------------------------------------------------
extern "C" void kernel_launch(void* const* d_in, const int* in_sizes, int n_in,
                              void* d_out, int out_size)
{
    const float* img  = (const float*)d_in[0];
    const float* gaze = (const float*)d_in[1];
    const float* sal  = (const float*)d_in[2];
    float* out = (float*)d_out;

    dim3 g1(PARTS, NB);
    sal_reduce_kernel<<<g1, 256>>>(sal, gaze);
    warp_sample_kernel<<<NB * NH, 256>>>(img, gaze, out);
}

// round 7
// speedup vs baseline: 1.3273x; 1.0561x over previous
#include <cuda_runtime.h>
#include <cstdint>

#define NB 32
#define NH 512
#define NW 512
#define NHW (NH * NW)          // 262144
#define PARTS 64
#define CHUNK (NHW / PARTS)    // 4096
#define FOV 160.0f             // 0.3125 * 512
#define KCONST 106.496f        // 0.208  * 512

// scratch (no allocations allowed)
__device__ float g_part[NB * PARTS * 3];

// ---------------------------------------------------------------------------
// Kernel 1: per-(batch, part) partial sums of S, S*r, S*r^2
// grid = (PARTS, NB) = 2048 blocks x 256. 4 front-batched LDG.128 (MLP=4).
// ---------------------------------------------------------------------------
__global__ void __launch_bounds__(256) sal_reduce_kernel(
    const float* __restrict__ sal, const float* __restrict__ gaze)
{
    const int b = blockIdx.y;
    const int p = blockIdx.x;
    const float xg = __ldg(&gaze[2 * b]);
    const float yg = __ldg(&gaze[2 * b + 1]);
    const float4* S4 = (const float4*)(sal + (size_t)b * NHW + (size_t)p * CHUNK);
    const int base_lin = p * CHUNK;

    // front-batch all 4 LDG.128s for memory-level parallelism
    float4 v[4];
    #pragma unroll
    for (int it = 0; it < 4; it++)
        v[it] = __ldg(&S4[it * 256 + threadIdx.x]);

    float s0 = 0.f, s1 = 0.f, s2 = 0.f;
    #pragma unroll
    for (int it = 0; it < 4; it++) {
        int lin = base_lin + (it * 256 + threadIdx.x) * 4;
        float dy = (float)(lin >> 9) - yg;
        float dy2 = fmaf(dy, dy, 1e-6f);
        int x0 = lin & 511;
        #pragma unroll
        for (int k = 0; k < 4; k++) {
            float dx = (float)(x0 + k) - xg;
            float d2 = fmaf(dx, dx, dy2);
            float r  = d2 * rsqrtf(d2);       // r = sqrt(d2), 1 MUFU
            float sv = (&v[it].x)[k];
            s0 += sv;
            s1 = fmaf(sv, r, s1);
            s2 = fmaf(sv * r, r, s2);
        }
    }

    // block reduction
    __shared__ float sh[3][8];
    #pragma unroll
    for (int off = 16; off; off >>= 1) {
        s0 += __shfl_down_sync(0xffffffffu, s0, off);
        s1 += __shfl_down_sync(0xffffffffu, s1, off);
        s2 += __shfl_down_sync(0xffffffffu, s2, off);
    }
    const int wid = threadIdx.x >> 5, lane = threadIdx.x & 31;
    if (lane == 0) { sh[0][wid] = s0; sh[1][wid] = s1; sh[2][wid] = s2; }
    __syncthreads();
    if (wid == 0) {
        s0 = (lane < 8) ? sh[0][lane] : 0.f;
        s1 = (lane < 8) ? sh[1][lane] : 0.f;
        s2 = (lane < 8) ? sh[2][lane] : 0.f;
        #pragma unroll
        for (int off = 4; off; off >>= 1) {
            s0 += __shfl_down_sync(0xffffffffu, s0, off);
            s1 += __shfl_down_sync(0xffffffffu, s1, off);
            s2 += __shfl_down_sync(0xffffffffu, s2, off);
        }
        if (lane == 0) {
            float* dst = &g_part[(b * PARTS + p) * 3];
            dst[0] = s0; dst[1] = s1; dst[2] = s2;
        }
    }
}

// ---------------------------------------------------------------------------
// Kernel 2: warp + bilinear + quantize.  One block = one (batch,row).
// Each of 256 threads handles pixels x and x+256 (lane stride 1).
// Geometry facts used to strip instructions:
//   coef < 1  =>  sample point lies between gaze and pixel => inside image.
//   Hence no validity masks needed; a single clamp of fx,fy to [0,511]
//   guards fp round-off, x1=x0+1 / y1=y0+1 always in-bounds via min(...,510).
//   The reference's [-1,1] normalize round-trip is the identity (1e-5 px
//   jitter, output-continuous) => skipped.
// ---------------------------------------------------------------------------
__global__ void __launch_bounds__(256) warp_sample_kernel(
    const float* __restrict__ img, const float* __restrict__ gaze,
    float* __restrict__ out)
{
    const int b = blockIdx.x >> 9;
    const int y = blockIdx.x & 511;

    __shared__ float red[3][2];
    __shared__ float sprm[6];   // xg, yg, fe, coef, invden, addc

    // per-block parameter computation (threads 0..63)
    if (threadIdx.x < 64) {
        const float* src = &g_part[(b * PARTS + threadIdx.x) * 3];
        float a0 = src[0], a1 = src[1], a2 = src[2];
        #pragma unroll
        for (int off = 16; off; off >>= 1) {
            a0 += __shfl_down_sync(0xffffffffu, a0, off);
            a1 += __shfl_down_sync(0xffffffffu, a1, off);
            a2 += __shfl_down_sync(0xffffffffu, a2, off);
        }
        if ((threadIdx.x & 31) == 0) {
            red[0][threadIdx.x >> 5] = a0;
            red[1][threadIdx.x >> 5] = a1;
            red[2][threadIdx.x >> 5] = a2;
        }
    }
    __syncthreads();
    if (threadIdx.x == 0) {
        float s0 = red[0][0] + red[0][1];
        float s1 = red[1][0] + red[1][1];
        float s2 = red[2][0] + red[2][1];
        const float xg = __ldg(&gaze[2 * b]);
        const float yg = __ldg(&gaze[2 * b + 1]);
        float inv = 1.0f / (s0 + 1e-6f);
        float mean_r  = s1 * inv;
        float mean_r2 = s2 * inv;
        float var = mean_r2 - mean_r * mean_r;
        float std_r = sqrtf(fmaxf(var, 0.0f));
        // r_max attained at an image corner (r monotone in |dx|,|dy|)
        float mdx = fmaxf(xg, 511.0f - xg);
        float mdy = fmaxf(yg, 511.0f - yg);
        float r_max = sqrtf(mdx * mdx + mdy * mdy + 1e-6f);
        float fe = FOV * (1.0f + 0.5f * (std_r / r_max));
        // max r_tfm = peri(r_max)  (monotone, r_max > fe always)
        float denom = 2.0f * (fe + KCONST);
        float addc  = (fe - KCONST) * 0.5f;
        float t = r_max + KCONST;
        float rtfm_max = t * t / denom + addc;
        float coef = r_max / (rtfm_max + 1e-6f);
        sprm[0] = xg; sprm[1] = yg; sprm[2] = fe;
        sprm[3] = coef; sprm[4] = 1.0f / denom; sprm[5] = addc;
    }
    __syncthreads();

    const float xg     = sprm[0];
    const float yg     = sprm[1];
    const float fe     = sprm[2];
    const float coef   = sprm[3];
    const float invden = sprm[4];
    const float addc   = sprm[5];

    const float dy  = (float)y - yg;
    const float dy2 = fmaf(dy, dy, 1e-6f);
    const float* imb = img + (size_t)b * 3 * NHW;
    float* outb = out + (size_t)b * 3 * NHW + y * NW;

    int   oo[2];
    float mm[2][4];

    #pragma unroll
    for (int p = 0; p < 2; p++) {
        const int x = threadIdx.x + p * 256;
        float dx = (float)x - xg;
        float d2 = fmaf(dx, dx, dy2);
        float invr = rsqrtf(d2);
        float r    = d2 * invr;

        float t  = r + KCONST;
        float rp = fmaf(t * t, invden, addc);
        float rt = (r < fe) ? r : rp;
        float rn = coef * rt;
        float fx = fmaf(dx * invr, rn, xg);   // == reference up to 1e-5 px
        float fy = fmaf(dy * invr, rn, yg);

        fx = fminf(fmaxf(fx, 0.0f), 511.0f);
        fy = fminf(fmaxf(fy, 0.0f), 511.0f);

        int x0i = min((int)fx, 510);          // trunc == floor (fx >= 0)
        int y0i = min((int)fy, 510);
        float wx1 = fx - (float)x0i;
        float wy1 = fy - (float)y0i;
        float wx0 = 1.0f - wx1;
        float wy0 = 1.0f - wy1;

        mm[p][0] = wy0 * wx0;
        mm[p][1] = wy0 * wx1;
        mm[p][2] = wy1 * wx0;
        mm[p][3] = wy1 * wx1;
        oo[p] = y0i * NW + x0i;               // +1, +512, +513 all in-bounds
    }

    // front-batch all 24 gather loads (addresses: 1 IMAD + 3 IADD per set)
    float g[2][12];
    #pragma unroll
    for (int p = 0; p < 2; p++) {
        #pragma unroll
        for (int c = 0; c < 3; c++) {
            const float* ic = imb + (size_t)c * NHW + oo[p];
            g[p][c * 4 + 0] = __ldg(ic);
            g[p][c * 4 + 1] = __ldg(ic + 1);
            g[p][c * 4 + 2] = __ldg(ic + NW);
            g[p][c * 4 + 3] = __ldg(ic + NW + 1);
        }
    }

    #pragma unroll
    for (int p = 0; p < 2; p++) {
        #pragma unroll
        for (int c = 0; c < 3; c++) {
            float v = g[p][c * 4 + 0] * mm[p][0] + g[p][c * 4 + 1] * mm[p][1] +
                      g[p][c * 4 + 2] * mm[p][2] + g[p][c * 4 + 3] * mm[p][3];
            v = fminf(fmaxf(v, 0.0f), 255.0f);
            // u8 quantization (trunc, matches XLA), stored f32, streaming
            __stcs(outb + (size_t)c * NHW + threadIdx.x + p * 256, truncf(v));
        }
    }
}

// ---------------------------------------------------------------------------
extern "C" void kernel_launch(void* const* d_in, const int* in_sizes, int n_in,
                              void* d_out, int out_size)
{
    const float* img  = (const float*)d_in[0];
    const float* gaze = (const float*)d_in[1];
    const float* sal  = (const float*)d_in[2];
    float* out = (float*)d_out;

    dim3 g1(PARTS, NB);
    sal_reduce_kernel<<<g1, 256>>>(sal, gaze);
    warp_sample_kernel<<<NB * NH, 256>>>(img, gaze, out);
}